// round 1
// baseline (speedup 1.0000x reference)
#include <cuda_runtime.h>
#include <math.h>

// Problem constants
#define CCH   512          // channels
#define NPIX  4096         // W*H
#define BATCH 8
#define NH    8
#define HD    64

// ---------------------------------------------------------------------------
// Scratch (no allocations allowed): Q, K, V projections; Q is reused as Y
// after the logits kernel has consumed it. A holds softmaxed attention.
// ---------------------------------------------------------------------------
__device__ float g_Q[(size_t)BATCH * CCH * NPIX];   // 64 MiB (later: Y)
__device__ float g_K[(size_t)BATCH * CCH * NPIX];   // 64 MiB
__device__ float g_V[(size_t)BATCH * CCH * NPIX];   // 64 MiB
__device__ float g_A[(size_t)BATCH * HD * NH * NH]; // [b][d][h][h'] 128 KiB

// ---------------------------------------------------------------------------
// gemm512: out[b, m, n] = sum_c W[m,c] * X[b,c,n] + bias[m] (+ R[b,m,n])
//   W:   512x512 row-major
//   X:   (B, 512, 4096) contiguous
//   out: (B, 512, 4096) contiguous
// Block tile 128x128, K-tile 8, 256 threads, 8x8 per-thread microtile.
// grid = (NPIX/128, CCH/128, BATCH)
// ---------------------------------------------------------------------------
template<bool RESID>
__global__ void __launch_bounds__(256) gemm512(
    const float* __restrict__ W, const float* __restrict__ bias,
    const float* __restrict__ X, const float* __restrict__ R,
    float* __restrict__ out)
{
    const int b     = blockIdx.z;
    const int mBase = blockIdx.y * 128;
    const int nBase = blockIdx.x * 128;
    const float* Xb = X + (size_t)b * CCH * NPIX;

    __shared__ __align__(16) float As[8][128];   // transposed W tile: [k][m]
    __shared__ __align__(16) float Bs[8][128];   // [k][n]

    const int tid = threadIdx.x;
    const int tx  = tid & 15;        // 0..15 -> n microtile
    const int ty  = tid >> 4;        // 0..15 -> m microtile

    // A-tile load map: 128 rows x 8 cols = 256 float4; row = tid/2, half = tid&1
    const int arow = tid >> 1;
    const int acv  = (tid & 1) * 4;
    // B-tile load map: 8 rows x 128 cols = 256 float4; row = tid/32
    const int brow = tid >> 5;
    const int bcv  = (tid & 31) * 4;

    float acc[8][8];
    #pragma unroll
    for (int i = 0; i < 8; i++)
        #pragma unroll
        for (int j = 0; j < 8; j++) acc[i][j] = 0.f;

    for (int k0 = 0; k0 < CCH; k0 += 8) {
        float4 av = *reinterpret_cast<const float4*>(
            &W[(size_t)(mBase + arow) * CCH + k0 + acv]);
        float4 bv = *reinterpret_cast<const float4*>(
            &Xb[(size_t)(k0 + brow) * NPIX + nBase + bcv]);

        __syncthreads();   // previous iteration's consumers done
        As[acv + 0][arow] = av.x;
        As[acv + 1][arow] = av.y;
        As[acv + 2][arow] = av.z;
        As[acv + 3][arow] = av.w;
        *reinterpret_cast<float4*>(&Bs[brow][bcv]) = bv;
        __syncthreads();

        #pragma unroll
        for (int kk = 0; kk < 8; kk++) {
            float am[8], bn[8];
            #pragma unroll
            for (int i = 0; i < 8; i++) am[i] = As[kk][ty * 8 + i];
            #pragma unroll
            for (int j = 0; j < 8; j++) bn[j] = Bs[kk][tx * 8 + j];
            #pragma unroll
            for (int i = 0; i < 8; i++)
                #pragma unroll
                for (int j = 0; j < 8; j++)
                    acc[i][j] += am[i] * bn[j];
        }
    }

    // Epilogue: bias (+ residual), vectorized stores
    #pragma unroll
    for (int i = 0; i < 8; i++) {
        const int m = mBase + ty * 8 + i;
        const float bi = bias[m];
        const size_t rowoff = ((size_t)b * CCH + m) * NPIX + nBase + tx * 8;
        #pragma unroll
        for (int j = 0; j < 8; j += 4) {
            float4 v;
            v.x = acc[i][j + 0] + bi;
            v.y = acc[i][j + 1] + bi;
            v.z = acc[i][j + 2] + bi;
            v.w = acc[i][j + 3] + bi;
            if (RESID) {
                float4 r = *reinterpret_cast<const float4*>(&R[rowoff + j]);
                v.x += r.x; v.y += r.y; v.z += r.z; v.w += r.w;
            }
            *reinterpret_cast<float4*>(&out[rowoff + j]) = v;
        }
    }
}

// ---------------------------------------------------------------------------
// attn_logits: per (b,d) block computes L[h][h'] = sum_n Q[b,h*64+d,n]*K[b,h'*64+d,n]
// then A = softmax(L / 8) over h'.
// grid = BATCH*HD blocks, 256 threads.
// ---------------------------------------------------------------------------
__global__ void __launch_bounds__(256) attn_logits(
    const float* __restrict__ Q, const float* __restrict__ Kp,
    float* __restrict__ A)
{
    const int bd = blockIdx.x;           // b*64 + d
    const int b  = bd >> 6;
    const int d  = bd & 63;
    const float* Qb = Q  + (size_t)b * CCH * NPIX + (size_t)d * NPIX;
    const float* Kb = Kp + (size_t)b * CCH * NPIX + (size_t)d * NPIX;

    float acc[64];
    #pragma unroll
    for (int e = 0; e < 64; e++) acc[e] = 0.f;

    for (int n = threadIdx.x; n < NPIX; n += 256) {
        float q[8], k[8];
        #pragma unroll
        for (int h = 0; h < 8; h++) {
            q[h] = Qb[(size_t)h * HD * NPIX + n];
            k[h] = Kb[(size_t)h * HD * NPIX + n];
        }
        #pragma unroll
        for (int i = 0; i < 8; i++)
            #pragma unroll
            for (int j = 0; j < 8; j++)
                acc[i * 8 + j] += q[i] * k[j];
    }

    const int lane = threadIdx.x & 31;
    const int warp = threadIdx.x >> 5;
    __shared__ float red[8][64];
    #pragma unroll
    for (int e = 0; e < 64; e++) {
        float v = acc[e];
        #pragma unroll
        for (int o = 16; o; o >>= 1) v += __shfl_down_sync(0xffffffffu, v, o);
        if (lane == 0) red[warp][e] = v;
    }
    __syncthreads();

    __shared__ float L[64];
    if (threadIdx.x < 64) {
        float s = 0.f;
        #pragma unroll
        for (int w = 0; w < 8; w++) s += red[w][threadIdx.x];
        L[threadIdx.x] = s * 0.125f;     // / sqrt(hd) = / 8
    }
    __syncthreads();

    if (threadIdx.x < 8) {
        const int h = threadIdx.x;
        float m = -INFINITY;
        #pragma unroll
        for (int j = 0; j < 8; j++) m = fmaxf(m, L[h * 8 + j]);
        float e[8], s = 0.f;
        #pragma unroll
        for (int j = 0; j < 8; j++) { e[j] = expf(L[h * 8 + j] - m); s += e[j]; }
        const float inv = 1.f / s;
        #pragma unroll
        for (int j = 0; j < 8; j++)
            A[(size_t)bd * 64 + h * 8 + j] = e[j] * inv;
    }
}

// ---------------------------------------------------------------------------
// mix: Y[b, h*64+d, n] = gamma * sum_h' A[b,d,h,h'] * V[b, h'*64+d, n]
// grid = (NPIX/256, BATCH*HD), 256 threads.
// ---------------------------------------------------------------------------
__global__ void __launch_bounds__(256) mix_kernel(
    const float* __restrict__ A, const float* __restrict__ V,
    const float* __restrict__ gamma, float* __restrict__ Y)
{
    const int bd = blockIdx.y;
    const int b  = bd >> 6;
    const int d  = bd & 63;

    __shared__ float a[64];
    if (threadIdx.x < 64)
        a[threadIdx.x] = A[(size_t)bd * 64 + threadIdx.x] * gamma[0];
    __syncthreads();

    const int n = blockIdx.x * 256 + threadIdx.x;
    const size_t base = (size_t)b * CCH * NPIX + (size_t)d * NPIX + n;

    float v[8];
    #pragma unroll
    for (int h = 0; h < 8; h++) v[h] = V[base + (size_t)h * HD * NPIX];
    #pragma unroll
    for (int h = 0; h < 8; h++) {
        float y = 0.f;
        #pragma unroll
        for (int j = 0; j < 8; j++) y += a[h * 8 + j] * v[j];
        Y[base + (size_t)h * HD * NPIX] = y;
    }
}

// ---------------------------------------------------------------------------
// kernel_launch
// Input order (metadata): x, Wq, bq, Wk, bk, Wv, bv, Wo, bo, gamma
// ---------------------------------------------------------------------------
extern "C" void kernel_launch(void* const* d_in, const int* in_sizes, int n_in,
                              void* d_out, int out_size)
{
    const float* x     = (const float*)d_in[0];
    const float* Wq    = (const float*)d_in[1];
    const float* bq    = (const float*)d_in[2];
    const float* Wk    = (const float*)d_in[3];
    const float* bk    = (const float*)d_in[4];
    const float* Wv    = (const float*)d_in[5];
    const float* bv    = (const float*)d_in[6];
    const float* Wo    = (const float*)d_in[7];
    const float* bo    = (const float*)d_in[8];
    const float* gamma = (const float*)d_in[9];
    float* out = (float*)d_out;

    float *Qp, *Kp, *Vp, *Ap;
    cudaGetSymbolAddress((void**)&Qp, g_Q);
    cudaGetSymbolAddress((void**)&Kp, g_K);
    cudaGetSymbolAddress((void**)&Vp, g_V);
    cudaGetSymbolAddress((void**)&Ap, g_A);

    dim3 gg(NPIX / 128, CCH / 128, BATCH);   // (32, 4, 8)

    // Q, K, V projections (bias fused)
    gemm512<false><<<gg, 256>>>(Wq, bq, x, nullptr, Qp);
    gemm512<false><<<gg, 256>>>(Wk, bk, x, nullptr, Kp);
    gemm512<false><<<gg, 256>>>(Wv, bv, x, nullptr, Vp);

    // Attention logits + softmax (tiny)
    attn_logits<<<BATCH * HD, 256>>>(Qp, Kp, Ap);

    // Head mixing with gamma folded in; reuse Q buffer as Y
    dim3 gm(NPIX / 256, BATCH * HD);
    mix_kernel<<<gm, 256>>>(Ap, Vp, gamma, Qp);

    // Output projection + bias + residual
    gemm512<true><<<gg, 256>>>(Wo, bo, Qp, x, out);
}

// round 2
// speedup vs baseline: 1.0021x; 1.0021x over previous
#include <cuda_runtime.h>
#include <math.h>

// Problem constants
#define CCH   512          // channels
#define NPIX  4096         // W*H
#define BATCH 8
#define NH    8
#define HD    64

// ---------------------------------------------------------------------------
// Scratch (no allocations allowed): Q, K, V projections; Q is reused as Y
// after the logits kernel has consumed it. A holds softmaxed attention.
// ---------------------------------------------------------------------------
__device__ float g_Q[(size_t)BATCH * CCH * NPIX];   // 64 MiB (later: Y)
__device__ float g_K[(size_t)BATCH * CCH * NPIX];   // 64 MiB
__device__ float g_V[(size_t)BATCH * CCH * NPIX];   // 64 MiB
__device__ float g_A[(size_t)BATCH * HD * NH * NH]; // [b][d][h][h'] 128 KiB

// ---------------------------------------------------------------------------
// gemm512: out[b, m, n] = sum_c W[m,c] * X[b,c,n] + bias[m] (+ R[b,m,n])
//   W:   512x512 row-major
//   X:   (B, 512, 4096) contiguous
//   out: (B, 512, 4096) contiguous
// Block tile 128x128, K-tile 8, 256 threads, 8x8 per-thread microtile.
// grid = (NPIX/128, CCH/128, BATCH)
// ---------------------------------------------------------------------------
template<bool RESID>
__global__ void __launch_bounds__(256) gemm512(
    const float* __restrict__ W, const float* __restrict__ bias,
    const float* __restrict__ X, const float* __restrict__ R,
    float* __restrict__ out)
{
    const int b     = blockIdx.z;
    const int mBase = blockIdx.y * 128;
    const int nBase = blockIdx.x * 128;
    const float* Xb = X + (size_t)b * CCH * NPIX;

    __shared__ __align__(16) float As[8][128];   // transposed W tile: [k][m]
    __shared__ __align__(16) float Bs[8][128];   // [k][n]

    const int tid = threadIdx.x;
    const int tx  = tid & 15;        // 0..15 -> n microtile
    const int ty  = tid >> 4;        // 0..15 -> m microtile

    // A-tile load map: 128 rows x 8 cols = 256 float4; row = tid/2, half = tid&1
    const int arow = tid >> 1;
    const int acv  = (tid & 1) * 4;
    // B-tile load map: 8 rows x 128 cols = 256 float4; row = tid/32
    const int brow = tid >> 5;
    const int bcv  = (tid & 31) * 4;

    float acc[8][8];
    #pragma unroll
    for (int i = 0; i < 8; i++)
        #pragma unroll
        for (int j = 0; j < 8; j++) acc[i][j] = 0.f;

    for (int k0 = 0; k0 < CCH; k0 += 8) {
        float4 av = *reinterpret_cast<const float4*>(
            &W[(size_t)(mBase + arow) * CCH + k0 + acv]);
        float4 bv = *reinterpret_cast<const float4*>(
            &Xb[(size_t)(k0 + brow) * NPIX + nBase + bcv]);

        __syncthreads();   // previous iteration's consumers done
        As[acv + 0][arow] = av.x;
        As[acv + 1][arow] = av.y;
        As[acv + 2][arow] = av.z;
        As[acv + 3][arow] = av.w;
        *reinterpret_cast<float4*>(&Bs[brow][bcv]) = bv;
        __syncthreads();

        #pragma unroll
        for (int kk = 0; kk < 8; kk++) {
            float am[8], bn[8];
            #pragma unroll
            for (int i = 0; i < 8; i++) am[i] = As[kk][ty * 8 + i];
            #pragma unroll
            for (int j = 0; j < 8; j++) bn[j] = Bs[kk][tx * 8 + j];
            #pragma unroll
            for (int i = 0; i < 8; i++)
                #pragma unroll
                for (int j = 0; j < 8; j++)
                    acc[i][j] += am[i] * bn[j];
        }
    }

    // Epilogue: bias (+ residual), vectorized stores
    #pragma unroll
    for (int i = 0; i < 8; i++) {
        const int m = mBase + ty * 8 + i;
        const float bi = bias[m];
        const size_t rowoff = ((size_t)b * CCH + m) * NPIX + nBase + tx * 8;
        #pragma unroll
        for (int j = 0; j < 8; j += 4) {
            float4 v;
            v.x = acc[i][j + 0] + bi;
            v.y = acc[i][j + 1] + bi;
            v.z = acc[i][j + 2] + bi;
            v.w = acc[i][j + 3] + bi;
            if (RESID) {
                float4 r = *reinterpret_cast<const float4*>(&R[rowoff + j]);
                v.x += r.x; v.y += r.y; v.z += r.z; v.w += r.w;
            }
            *reinterpret_cast<float4*>(&out[rowoff + j]) = v;
        }
    }
}

// ---------------------------------------------------------------------------
// attn_logits: per (b,d) block computes L[h][h'] = sum_n Q[b,h*64+d,n]*K[b,h'*64+d,n]
// then A = softmax(L / 8) over h'.
// grid = BATCH*HD blocks, 256 threads.
// ---------------------------------------------------------------------------
__global__ void __launch_bounds__(256) attn_logits(
    const float* __restrict__ Q, const float* __restrict__ Kp,
    float* __restrict__ A)
{
    const int bd = blockIdx.x;           // b*64 + d
    const int b  = bd >> 6;
    const int d  = bd & 63;
    const float* Qb = Q  + (size_t)b * CCH * NPIX + (size_t)d * NPIX;
    const float* Kb = Kp + (size_t)b * CCH * NPIX + (size_t)d * NPIX;

    float acc[64];
    #pragma unroll
    for (int e = 0; e < 64; e++) acc[e] = 0.f;

    for (int n = threadIdx.x; n < NPIX; n += 256) {
        float q[8], k[8];
        #pragma unroll
        for (int h = 0; h < 8; h++) {
            q[h] = Qb[(size_t)h * HD * NPIX + n];
            k[h] = Kb[(size_t)h * HD * NPIX + n];
        }
        #pragma unroll
        for (int i = 0; i < 8; i++)
            #pragma unroll
            for (int j = 0; j < 8; j++)
                acc[i * 8 + j] += q[i] * k[j];
    }

    const int lane = threadIdx.x & 31;
    const int warp = threadIdx.x >> 5;
    __shared__ float red[8][64];
    #pragma unroll
    for (int e = 0; e < 64; e++) {
        float v = acc[e];
        #pragma unroll
        for (int o = 16; o; o >>= 1) v += __shfl_down_sync(0xffffffffu, v, o);
        if (lane == 0) red[warp][e] = v;
    }
    __syncthreads();

    __shared__ float L[64];
    if (threadIdx.x < 64) {
        float s = 0.f;
        #pragma unroll
        for (int w = 0; w < 8; w++) s += red[w][threadIdx.x];
        L[threadIdx.x] = s * 0.125f;     // / sqrt(hd) = / 8
    }
    __syncthreads();

    if (threadIdx.x < 8) {
        const int h = threadIdx.x;
        float m = -INFINITY;
        #pragma unroll
        for (int j = 0; j < 8; j++) m = fmaxf(m, L[h * 8 + j]);
        float e[8], s = 0.f;
        #pragma unroll
        for (int j = 0; j < 8; j++) { e[j] = expf(L[h * 8 + j] - m); s += e[j]; }
        const float inv = 1.f / s;
        #pragma unroll
        for (int j = 0; j < 8; j++)
            A[(size_t)bd * 64 + h * 8 + j] = e[j] * inv;
    }
}

// ---------------------------------------------------------------------------
// mix: Y[b, h*64+d, n] = gamma * sum_h' A[b,d,h,h'] * V[b, h'*64+d, n]
// grid = (NPIX/256, BATCH*HD), 256 threads.
// ---------------------------------------------------------------------------
__global__ void __launch_bounds__(256) mix_kernel(
    const float* __restrict__ A, const float* __restrict__ V,
    const float* __restrict__ gamma, float* __restrict__ Y)
{
    const int bd = blockIdx.y;
    const int b  = bd >> 6;
    const int d  = bd & 63;

    __shared__ float a[64];
    if (threadIdx.x < 64)
        a[threadIdx.x] = A[(size_t)bd * 64 + threadIdx.x] * gamma[0];
    __syncthreads();

    const int n = blockIdx.x * 256 + threadIdx.x;
    const size_t base = (size_t)b * CCH * NPIX + (size_t)d * NPIX + n;

    float v[8];
    #pragma unroll
    for (int h = 0; h < 8; h++) v[h] = V[base + (size_t)h * HD * NPIX];
    #pragma unroll
    for (int h = 0; h < 8; h++) {
        float y = 0.f;
        #pragma unroll
        for (int j = 0; j < 8; j++) y += a[h * 8 + j] * v[j];
        Y[base + (size_t)h * HD * NPIX] = y;
    }
}

// ---------------------------------------------------------------------------
// kernel_launch
// Input order (metadata): x, Wq, bq, Wk, bk, Wv, bv, Wo, bo, gamma
// ---------------------------------------------------------------------------
extern "C" void kernel_launch(void* const* d_in, const int* in_sizes, int n_in,
                              void* d_out, int out_size)
{
    const float* x     = (const float*)d_in[0];
    const float* Wq    = (const float*)d_in[1];
    const float* bq    = (const float*)d_in[2];
    const float* Wk    = (const float*)d_in[3];
    const float* bk    = (const float*)d_in[4];
    const float* Wv    = (const float*)d_in[5];
    const float* bv    = (const float*)d_in[6];
    const float* Wo    = (const float*)d_in[7];
    const float* bo    = (const float*)d_in[8];
    const float* gamma = (const float*)d_in[9];
    float* out = (float*)d_out;

    float *Qp, *Kp, *Vp, *Ap;
    cudaGetSymbolAddress((void**)&Qp, g_Q);
    cudaGetSymbolAddress((void**)&Kp, g_K);
    cudaGetSymbolAddress((void**)&Vp, g_V);
    cudaGetSymbolAddress((void**)&Ap, g_A);

    dim3 gg(NPIX / 128, CCH / 128, BATCH);   // (32, 4, 8)

    // Q, K, V projections (bias fused)
    gemm512<false><<<gg, 256>>>(Wq, bq, x, nullptr, Qp);
    gemm512<false><<<gg, 256>>>(Wk, bk, x, nullptr, Kp);
    gemm512<false><<<gg, 256>>>(Wv, bv, x, nullptr, Vp);

    // Attention logits + softmax (tiny)
    attn_logits<<<BATCH * HD, 256>>>(Qp, Kp, Ap);

    // Head mixing with gamma folded in; reuse Q buffer as Y
    dim3 gm(NPIX / 256, BATCH * HD);
    mix_kernel<<<gm, 256>>>(Ap, Vp, gamma, Qp);

    // Output projection + bias + residual
    gemm512<true><<<gg, 256>>>(Wo, bo, Qp, x, out);
}

// round 4
// speedup vs baseline: 2.3074x; 2.3027x over previous
#include <cuda_runtime.h>
#include <cuda_fp16.h>
#include <math.h>
#include <stdint.h>

#define CCH   512
#define NPIX  4096
#define BATCH 8
#define HD    64

// ---------------- scratch (no allocations allowed) ----------------
__device__ float g_Q[(size_t)BATCH * CCH * NPIX];   // Q, later reused as Y
__device__ float g_K[(size_t)BATCH * CCH * NPIX];
__device__ float g_V[(size_t)BATCH * CCH * NPIX];
__device__ float g_A[BATCH * HD * 8 * 8];
__device__ __half g_Wh[4 * CCH * CCH];              // weights hi
__device__ __half g_Wl[4 * CCH * CCH];              // weights lo

// ---------------- mma/ldmatrix helpers ----------------
__device__ __forceinline__ uint32_t smem_u32(const void* p) {
    uint32_t a;
    asm("{ .reg .u64 t; cvta.to.shared.u64 t, %1; cvt.u32.u64 %0, t; }" : "=r"(a) : "l"(p));
    return a;
}
__device__ __forceinline__ void ldsm4(uint32_t* r, uint32_t addr) {
    asm volatile("ldmatrix.sync.aligned.m8n8.x4.shared.b16 {%0,%1,%2,%3}, [%4];"
                 : "=r"(r[0]), "=r"(r[1]), "=r"(r[2]), "=r"(r[3]) : "r"(addr));
}
__device__ __forceinline__ void ldsm4t(uint32_t* r, uint32_t addr) {
    asm volatile("ldmatrix.sync.aligned.m8n8.x4.trans.shared.b16 {%0,%1,%2,%3}, [%4];"
                 : "=r"(r[0]), "=r"(r[1]), "=r"(r[2]), "=r"(r[3]) : "r"(addr));
}
__device__ __forceinline__ void mma16816(float* c, const uint32_t* a, uint32_t b0, uint32_t b1) {
    asm volatile("mma.sync.aligned.m16n8k16.row.col.f32.f16.f16.f32 "
                 "{%0,%1,%2,%3}, {%4,%5,%6,%7}, {%8,%9}, {%0,%1,%2,%3};"
                 : "+f"(c[0]), "+f"(c[1]), "+f"(c[2]), "+f"(c[3])
                 : "r"(a[0]), "r"(a[1]), "r"(a[2]), "r"(a[3]), "r"(b0), "r"(b1));
}

// SMEM layout (halfs): A padded to 40 halfs/row (80B), B to 136 (272B)
#define A_ST 40
#define B_ST 136
#define A_MAT (128 * A_ST)        // 5120 halfs
#define B_MAT (32 * B_ST)         // 4352 halfs
#define OFF_AH 0
#define OFF_AL A_MAT
#define OFF_BH (2 * A_MAT)
#define OFF_BL (2 * A_MAT + B_MAT)
#define SM_HALFS (2 * A_MAT + 2 * B_MAT)   // 18944 halfs = 37888 B

// ---------------------------------------------------------------------------
// hgemm: out[b][m][n] = sum_k W[m][k] * X[b][k][n] + bias[m] (+ resid)
// W pre-split to fp16 hi/lo (Ah, Al); X fp32 converted in-kernel.
// Double-fp16, 3 mma passes: Ah*Bh + Ah*Bl + Al*Bh.
// grid (NPIX/128, CCH/128, B), 512 threads (16 warps, 4x4, 32x32 warp tiles)
// ---------------------------------------------------------------------------
template<bool RESID>
__global__ void __launch_bounds__(512, 1) hgemm(
    const __half* __restrict__ Ahg, const __half* __restrict__ Alg,
    const float* __restrict__ X, const float* __restrict__ bias,
    const float* __restrict__ resid, float* __restrict__ out)
{
    __shared__ __half sm[SM_HALFS];

    const int tid = threadIdx.x;
    const int lane = tid & 31, wid = tid >> 5;
    const int wm = wid >> 2, wn = wid & 3;
    const int b = blockIdx.z;
    const int m0 = blockIdx.y * 128, n0 = blockIdx.x * 128;
    const float* Xb = X + (size_t)b * CCH * NPIX;

    // global load maps
    const int ar = tid >> 2, ak = (tid & 3) * 8;       // A: 128 rows x 32 halfs
    const int br = tid >> 4, bn = (tid & 15) * 8;      // B: 32 rows x 128 floats

    // ldmatrix per-thread address components
    const int quad = lane >> 3, r8 = lane & 7;
    const int qlow = (quad & 1) * 8, qhi = (quad >> 1) * 8;
    const uint32_t sb = smem_u32(sm);

    float c[2][4][4];
    #pragma unroll
    for (int i = 0; i < 2; i++)
        #pragma unroll
        for (int j = 0; j < 4; j++)
            #pragma unroll
            for (int e = 0; e < 4; e++) c[i][j][e] = 0.f;

    uint4 pAh, pAl;
    float4 pB0, pB1;

    // prefetch chunk 0
    pAh = *(const uint4*)&Ahg[(size_t)(m0 + ar) * CCH + ak];
    pAl = *(const uint4*)&Alg[(size_t)(m0 + ar) * CCH + ak];
    pB0 = *(const float4*)&Xb[(size_t)br * NPIX + n0 + bn];
    pB1 = *(const float4*)&Xb[(size_t)br * NPIX + n0 + bn + 4];

    for (int ch = 0; ch < 16; ch++) {
        // store prefetched chunk to SMEM
        *(uint4*)&sm[OFF_AH + ar * A_ST + ak] = pAh;
        *(uint4*)&sm[OFF_AL + ar * A_ST + ak] = pAl;
        {
            float v[8] = {pB0.x, pB0.y, pB0.z, pB0.w, pB1.x, pB1.y, pB1.z, pB1.w};
            __half2 h2[4], l2[4];
            #pragma unroll
            for (int i = 0; i < 4; i++) {
                __half ha = __float2half_rn(v[2 * i]);
                __half hb = __float2half_rn(v[2 * i + 1]);
                h2[i] = __halves2half2(ha, hb);
                l2[i] = __halves2half2(__float2half_rn(v[2 * i]     - __half2float(ha)),
                                       __float2half_rn(v[2 * i + 1] - __half2float(hb)));
            }
            *(uint4*)&sm[OFF_BH + br * B_ST + bn] = *(uint4*)h2;
            *(uint4*)&sm[OFF_BL + br * B_ST + bn] = *(uint4*)l2;
        }
        __syncthreads();

        // prefetch next chunk while computing this one
        if (ch < 15) {
            const int k0 = (ch + 1) * 32;
            pAh = *(const uint4*)&Ahg[(size_t)(m0 + ar) * CCH + k0 + ak];
            pAl = *(const uint4*)&Alg[(size_t)(m0 + ar) * CCH + k0 + ak];
            pB0 = *(const float4*)&Xb[(size_t)(k0 + br) * NPIX + n0 + bn];
            pB1 = *(const float4*)&Xb[(size_t)(k0 + br) * NPIX + n0 + bn + 4];
        }

        // compute: 2 k16 steps
        #pragma unroll
        for (int k16 = 0; k16 < 2; k16++) {
            uint32_t ah[2][4], al[2][4], bh[2][4], bl[2][4];
            #pragma unroll
            for (int mi = 0; mi < 2; mi++) {
                const uint32_t off = 2 * ((uint32_t)(wm * 32 + mi * 16 + r8 + qlow) * A_ST
                                          + k16 * 16 + qhi);
                ldsm4(ah[mi], sb + 2 * OFF_AH + off);
                ldsm4(al[mi], sb + 2 * OFF_AL + off);
            }
            #pragma unroll
            for (int ni = 0; ni < 2; ni++) {
                const uint32_t off = 2 * ((uint32_t)(k16 * 16 + r8 + qlow) * B_ST
                                          + wn * 32 + ni * 16 + qhi);
                ldsm4t(bh[ni], sb + 2 * OFF_BH + off);
                ldsm4t(bl[ni], sb + 2 * OFF_BL + off);
            }
            #pragma unroll
            for (int mi = 0; mi < 2; mi++)
                #pragma unroll
                for (int j = 0; j < 4; j++) {
                    const int ni = j >> 1, s = (j & 1) * 2;
                    mma16816(c[mi][j], ah[mi], bh[ni][s], bh[ni][s + 1]);
                    mma16816(c[mi][j], ah[mi], bl[ni][s], bl[ni][s + 1]);
                    mma16816(c[mi][j], al[mi], bh[ni][s], bh[ni][s + 1]);
                }
        }
        __syncthreads();
    }

    // epilogue
    #pragma unroll
    for (int mi = 0; mi < 2; mi++) {
        #pragma unroll
        for (int rr = 0; rr < 2; rr++) {
            const int m = m0 + wm * 32 + mi * 16 + (lane >> 2) + rr * 8;
            const float bi = __ldg(&bias[m]);
            const size_t rowoff = ((size_t)b * CCH + m) * NPIX + n0 + wn * 32 + (lane & 3) * 2;
            #pragma unroll
            for (int j = 0; j < 4; j++) {
                float2 v;
                v.x = c[mi][j][rr * 2 + 0] + bi;
                v.y = c[mi][j][rr * 2 + 1] + bi;
                if (RESID) {
                    float2 r = *(const float2*)&resid[rowoff + j * 8];
                    v.x += r.x; v.y += r.y;
                }
                *(float2*)&out[rowoff + j * 8] = v;
            }
        }
    }
}

// ---------------------------------------------------------------------------
// prep_w: split 4 weight matrices fp32 -> fp16 hi/lo
// ---------------------------------------------------------------------------
__global__ void __launch_bounds__(256) prep_w(
    const float* __restrict__ Wq, const float* __restrict__ Wk,
    const float* __restrict__ Wv, const float* __restrict__ Wo)
{
    const int m = blockIdx.y;
    const size_t t = (size_t)blockIdx.x * 256 + threadIdx.x;
    const float* W = (m == 0) ? Wq : (m == 1) ? Wk : (m == 2) ? Wv : Wo;
    const float v = W[t];
    const __half h = __float2half_rn(v);
    g_Wh[(size_t)m * CCH * CCH + t] = h;
    g_Wl[(size_t)m * CCH * CCH + t] = __float2half_rn(v - __half2float(h));
}

// ---------------------------------------------------------------------------
// attn_logits (unchanged from round 1, known correct)
// ---------------------------------------------------------------------------
__global__ void __launch_bounds__(256) attn_logits(
    const float* __restrict__ Q, const float* __restrict__ Kp,
    float* __restrict__ A)
{
    const int bd = blockIdx.x;
    const int b  = bd >> 6;
    const int d  = bd & 63;
    const float* Qb = Q  + (size_t)b * CCH * NPIX + (size_t)d * NPIX;
    const float* Kb = Kp + (size_t)b * CCH * NPIX + (size_t)d * NPIX;

    float acc[64];
    #pragma unroll
    for (int e = 0; e < 64; e++) acc[e] = 0.f;

    for (int n = threadIdx.x; n < NPIX; n += 256) {
        float q[8], k[8];
        #pragma unroll
        for (int h = 0; h < 8; h++) {
            q[h] = Qb[(size_t)h * HD * NPIX + n];
            k[h] = Kb[(size_t)h * HD * NPIX + n];
        }
        #pragma unroll
        for (int i = 0; i < 8; i++)
            #pragma unroll
            for (int j = 0; j < 8; j++)
                acc[i * 8 + j] += q[i] * k[j];
    }

    const int lane = threadIdx.x & 31;
    const int warp = threadIdx.x >> 5;
    __shared__ float red[8][64];
    #pragma unroll
    for (int e = 0; e < 64; e++) {
        float v = acc[e];
        #pragma unroll
        for (int o = 16; o; o >>= 1) v += __shfl_down_sync(0xffffffffu, v, o);
        if (lane == 0) red[warp][e] = v;
    }
    __syncthreads();

    __shared__ float L[64];
    if (threadIdx.x < 64) {
        float s = 0.f;
        #pragma unroll
        for (int w = 0; w < 8; w++) s += red[w][threadIdx.x];
        L[threadIdx.x] = s * 0.125f;
    }
    __syncthreads();

    if (threadIdx.x < 8) {
        const int h = threadIdx.x;
        float m = -INFINITY;
        #pragma unroll
        for (int j = 0; j < 8; j++) m = fmaxf(m, L[h * 8 + j]);
        float e[8], s = 0.f;
        #pragma unroll
        for (int j = 0; j < 8; j++) { e[j] = expf(L[h * 8 + j] - m); s += e[j]; }
        const float inv = 1.f / s;
        #pragma unroll
        for (int j = 0; j < 8; j++)
            A[(size_t)bd * 64 + h * 8 + j] = e[j] * inv;
    }
}

// ---------------------------------------------------------------------------
// mix (unchanged from round 1)
// ---------------------------------------------------------------------------
__global__ void __launch_bounds__(256) mix_kernel(
    const float* __restrict__ A, const float* __restrict__ V,
    const float* __restrict__ gamma, float* __restrict__ Y)
{
    const int bd = blockIdx.y;
    const int b  = bd >> 6;
    const int d  = bd & 63;

    __shared__ float a[64];
    if (threadIdx.x < 64)
        a[threadIdx.x] = A[(size_t)bd * 64 + threadIdx.x] * gamma[0];
    __syncthreads();

    const int n = blockIdx.x * 256 + threadIdx.x;
    const size_t base = (size_t)b * CCH * NPIX + (size_t)d * NPIX + n;

    float v[8];
    #pragma unroll
    for (int h = 0; h < 8; h++) v[h] = V[base + (size_t)h * HD * NPIX];
    #pragma unroll
    for (int h = 0; h < 8; h++) {
        float y = 0.f;
        #pragma unroll
        for (int j = 0; j < 8; j++) y += a[h * 8 + j] * v[j];
        Y[base + (size_t)h * HD * NPIX] = y;
    }
}

// ---------------------------------------------------------------------------
extern "C" void kernel_launch(void* const* d_in, const int* in_sizes, int n_in,
                              void* d_out, int out_size)
{
    const float* x  = (const float*)d_in[0];
    const float* Wq = (const float*)d_in[1];
    const float* bq = (const float*)d_in[2];
    const float* Wk = (const float*)d_in[3];
    const float* bk = (const float*)d_in[4];
    const float* Wv = (const float*)d_in[5];
    const float* bv = (const float*)d_in[6];
    const float* Wo = (const float*)d_in[7];
    const float* bo = (const float*)d_in[8];
    const float* gm = (const float*)d_in[9];
    float* out = (float*)d_out;

    float *Qp, *Kp, *Vp, *Ap;
    __half *Wh, *Wl;
    cudaGetSymbolAddress((void**)&Qp, g_Q);
    cudaGetSymbolAddress((void**)&Kp, g_K);
    cudaGetSymbolAddress((void**)&Vp, g_V);
    cudaGetSymbolAddress((void**)&Ap, g_A);
    cudaGetSymbolAddress((void**)&Wh, g_Wh);
    cudaGetSymbolAddress((void**)&Wl, g_Wl);

    prep_w<<<dim3(CCH * CCH / 256, 4), 256>>>(Wq, Wk, Wv, Wo);

    const size_t WS = (size_t)CCH * CCH;
    dim3 gg(NPIX / 128, CCH / 128, BATCH);   // (32, 4, 8)
    hgemm<false><<<gg, 512>>>(Wh + 0 * WS, Wl + 0 * WS, x, bq, nullptr, Qp);
    hgemm<false><<<gg, 512>>>(Wh + 1 * WS, Wl + 1 * WS, x, bk, nullptr, Kp);
    hgemm<false><<<gg, 512>>>(Wh + 2 * WS, Wl + 2 * WS, x, bv, nullptr, Vp);

    attn_logits<<<BATCH * HD, 256>>>(Qp, Kp, Ap);

    dim3 gm2(NPIX / 256, BATCH * HD);
    mix_kernel<<<gm2, 256>>>(Ap, Vp, gm, Qp);   // Y -> g_Q

    hgemm<true><<<gg, 512>>>(Wh + 3 * WS, Wl + 3 * WS, Qp, bo, x, out);
}

// round 5
// speedup vs baseline: 2.3544x; 1.0204x over previous
#include <cuda_runtime.h>
#include <cuda_fp16.h>
#include <math.h>
#include <stdint.h>

#define CCH   512
#define NPIX  4096
#define BATCH 8
#define HD    64

// ---------------- scratch (no allocations allowed) ----------------
__device__ float g_Q[(size_t)BATCH * CCH * NPIX];
__device__ float g_K[(size_t)BATCH * CCH * NPIX];
__device__ float g_V[(size_t)BATCH * CCH * NPIX];
__device__ float g_A[BATCH * HD * 8 * 8];
__device__ __half g_Wh[4 * CCH * CCH];
__device__ __half g_Wl[4 * CCH * CCH];
__device__ __half g_Xh[(size_t)BATCH * CCH * NPIX];   // x split hi
__device__ __half g_Xl[(size_t)BATCH * CCH * NPIX];   // x split lo
__device__ __half g_Yh[(size_t)BATCH * CCH * NPIX];   // y split hi
__device__ __half g_Yl[(size_t)BATCH * CCH * NPIX];   // y split lo

// ---------------- helpers ----------------
__device__ __forceinline__ uint32_t smem_u32(const void* p) {
    uint32_t a;
    asm("{ .reg .u64 t; cvta.to.shared.u64 t, %1; cvt.u32.u64 %0, t; }" : "=r"(a) : "l"(p));
    return a;
}
__device__ __forceinline__ void cpasync16(uint32_t dst, const void* src) {
    asm volatile("cp.async.cg.shared.global [%0], [%1], 16;" :: "r"(dst), "l"(src));
}
#define CP_COMMIT() asm volatile("cp.async.commit_group;" ::: "memory")
template<int N> __device__ __forceinline__ void cp_wait() {
    asm volatile("cp.async.wait_group %0;" :: "n"(N) : "memory");
}
__device__ __forceinline__ void ldsm4(uint32_t* r, uint32_t addr) {
    asm volatile("ldmatrix.sync.aligned.m8n8.x4.shared.b16 {%0,%1,%2,%3}, [%4];"
                 : "=r"(r[0]), "=r"(r[1]), "=r"(r[2]), "=r"(r[3]) : "r"(addr));
}
__device__ __forceinline__ void ldsm4t(uint32_t* r, uint32_t addr) {
    asm volatile("ldmatrix.sync.aligned.m8n8.x4.trans.shared.b16 {%0,%1,%2,%3}, [%4];"
                 : "=r"(r[0]), "=r"(r[1]), "=r"(r[2]), "=r"(r[3]) : "r"(addr));
}
__device__ __forceinline__ void mma16816(float* c, const uint32_t* a, uint32_t b0, uint32_t b1) {
    asm volatile("mma.sync.aligned.m16n8k16.row.col.f32.f16.f16.f32 "
                 "{%0,%1,%2,%3}, {%4,%5,%6,%7}, {%8,%9}, {%0,%1,%2,%3};"
                 : "+f"(c[0]), "+f"(c[1]), "+f"(c[2]), "+f"(c[3])
                 : "r"(a[0]), "r"(a[1]), "r"(a[2]), "r"(a[3]), "r"(b0), "r"(b1));
}

// SMEM layout (halfs): A padded to 40 halfs/row (80B), B to 136 (272B)
#define A_ST 40
#define B_ST 136
#define A_MAT (128 * A_ST)              // 5120 halfs
#define B_MAT (32 * B_ST)               // 4352 halfs
#define OFF_AH 0
#define OFF_AL A_MAT
#define OFF_BH (2 * A_MAT)
#define OFF_BL (2 * A_MAT + B_MAT)
#define STAGE_HALFS (2 * A_MAT + 2 * B_MAT)       // 18944 halfs
#define NSTAGE 4
#define SMEM_BYTES (NSTAGE * STAGE_HALFS * 2)     // 151552 B
#define NCH 16

// ---------------------------------------------------------------------------
// hgemm: out[b][m][n] = sum_k W[m][k] * X[b][k][n] + bias[m] (+ resid)
// All operands pre-split fp16 hi/lo. Double-fp16, 3 mma passes.
// 4-stage cp.async pipeline, issue-ahead-2, 1 barrier per K-chunk.
// grid (NPIX/128, CCH/128, B), 512 threads (16 warps, 32x32 warp tiles)
// ---------------------------------------------------------------------------
template<bool RESID>
__global__ void __launch_bounds__(512, 1) hgemm(
    const __half* __restrict__ Whg, const __half* __restrict__ Wlg,
    const __half* __restrict__ Xhg, const __half* __restrict__ Xlg,
    const float* __restrict__ bias, const float* __restrict__ resid,
    float* __restrict__ out)
{
    extern __shared__ __half sm[];
    const uint32_t sb = smem_u32(sm);

    const int tid = threadIdx.x;
    const int lane = tid & 31, wid = tid >> 5;
    const int wm = wid >> 2, wn = wid & 3;
    const int b = blockIdx.z;
    const int m0 = blockIdx.y * 128, n0 = blockIdx.x * 128;
    const __half* Bh = Xhg + (size_t)b * CCH * NPIX;
    const __half* Bl = Xlg + (size_t)b * CCH * NPIX;

    // cp.async load maps: A 128 rows x 32 halfs (4x16B), B 32 rows x 128 halfs (16x16B)
    const int ar = tid >> 2, ak = (tid & 3) * 8;
    const int br = tid >> 4, bn = (tid & 15) * 8;

    // ldmatrix per-thread address components
    const int quad = lane >> 3, r8 = lane & 7;
    const int qlow = (quad & 1) * 8, qhi = (quad >> 1) * 8;

    float c[2][4][4];
    #pragma unroll
    for (int i = 0; i < 2; i++)
        #pragma unroll
        for (int j = 0; j < 4; j++)
            #pragma unroll
            for (int e = 0; e < 4; e++) c[i][j][e] = 0.f;

    // stage issue: chunk ch into stage s
    auto issue = [&](int s, int ch) {
        const int k0 = ch * 32;
        const uint32_t st = sb + 2 * (s * STAGE_HALFS);
        cpasync16(st + 2 * (OFF_AH + ar * A_ST + ak),
                  Whg + (size_t)(m0 + ar) * CCH + k0 + ak);
        cpasync16(st + 2 * (OFF_AL + ar * A_ST + ak),
                  Wlg + (size_t)(m0 + ar) * CCH + k0 + ak);
        cpasync16(st + 2 * (OFF_BH + br * B_ST + bn),
                  Bh + (size_t)(k0 + br) * NPIX + n0 + bn);
        cpasync16(st + 2 * (OFF_BL + br * B_ST + bn),
                  Bl + (size_t)(k0 + br) * NPIX + n0 + bn);
    };

    issue(0, 0); CP_COMMIT();
    issue(1, 1); CP_COMMIT();

    for (int ch = 0; ch < NCH; ch++) {
        const int s = ch & 3;
        if (ch + 2 < NCH) { issue((ch + 2) & 3, ch + 2); CP_COMMIT(); }
        if (ch + 2 < NCH)      cp_wait<2>();
        else if (ch + 1 < NCH) cp_wait<1>();
        else                   cp_wait<0>();
        __syncthreads();

        const uint32_t sbase = sb + 2 * (s * STAGE_HALFS);
        #pragma unroll
        for (int k16 = 0; k16 < 2; k16++) {
            uint32_t ah[2][4], al[2][4], bh[2][4], bl[2][4];
            #pragma unroll
            for (int mi = 0; mi < 2; mi++) {
                const uint32_t off = 2 * ((uint32_t)(wm * 32 + mi * 16 + r8 + qlow) * A_ST
                                          + k16 * 16 + qhi);
                ldsm4(ah[mi], sbase + 2 * OFF_AH + off);
                ldsm4(al[mi], sbase + 2 * OFF_AL + off);
            }
            #pragma unroll
            for (int ni = 0; ni < 2; ni++) {
                const uint32_t off = 2 * ((uint32_t)(k16 * 16 + r8 + qlow) * B_ST
                                          + wn * 32 + ni * 16 + qhi);
                ldsm4t(bh[ni], sbase + 2 * OFF_BH + off);
                ldsm4t(bl[ni], sbase + 2 * OFF_BL + off);
            }
            #pragma unroll
            for (int mi = 0; mi < 2; mi++)
                #pragma unroll
                for (int j = 0; j < 4; j++) {
                    const int ni = j >> 1, ss = (j & 1) * 2;
                    mma16816(c[mi][j], ah[mi], bh[ni][ss], bh[ni][ss + 1]);
                    mma16816(c[mi][j], ah[mi], bl[ni][ss], bl[ni][ss + 1]);
                    mma16816(c[mi][j], al[mi], bh[ni][ss], bh[ni][ss + 1]);
                }
        }
        __syncthreads();
    }

    // epilogue
    #pragma unroll
    for (int mi = 0; mi < 2; mi++) {
        #pragma unroll
        for (int rr = 0; rr < 2; rr++) {
            const int m = m0 + wm * 32 + mi * 16 + (lane >> 2) + rr * 8;
            const float bi = __ldg(&bias[m]);
            const size_t rowoff = ((size_t)b * CCH + m) * NPIX + n0 + wn * 32 + (lane & 3) * 2;
            #pragma unroll
            for (int j = 0; j < 4; j++) {
                float2 v;
                v.x = c[mi][j][rr * 2 + 0] + bi;
                v.y = c[mi][j][rr * 2 + 1] + bi;
                if (RESID) {
                    float2 r = *(const float2*)&resid[rowoff + j * 8];
                    v.x += r.x; v.y += r.y;
                }
                *(float2*)&out[rowoff + j * 8] = v;
            }
        }
    }
}

// ---------------------------------------------------------------------------
// prep_x: split fp32 -> fp16 hi/lo, 8 elems/thread (16B stores)
// ---------------------------------------------------------------------------
__global__ void __launch_bounds__(256) prep_x(
    const float* __restrict__ src, __half* __restrict__ hi, __half* __restrict__ lo)
{
    const size_t i = ((size_t)blockIdx.x * 256 + threadIdx.x) * 8;
    float4 v0 = *(const float4*)&src[i];
    float4 v1 = *(const float4*)&src[i + 4];
    const float v[8] = {v0.x, v0.y, v0.z, v0.w, v1.x, v1.y, v1.z, v1.w};
    __half h[8], l[8];
    #pragma unroll
    for (int e = 0; e < 8; e++) {
        h[e] = __float2half_rn(v[e]);
        l[e] = __float2half_rn(v[e] - __half2float(h[e]));
    }
    *(uint4*)&hi[i] = *(const uint4*)h;
    *(uint4*)&lo[i] = *(const uint4*)l;
}

__global__ void __launch_bounds__(256) prep_w(
    const float* __restrict__ Wq, const float* __restrict__ Wk,
    const float* __restrict__ Wv, const float* __restrict__ Wo)
{
    const int m = blockIdx.y;
    const size_t t = (size_t)blockIdx.x * 256 + threadIdx.x;
    const float* W = (m == 0) ? Wq : (m == 1) ? Wk : (m == 2) ? Wv : Wo;
    const float v = W[t];
    const __half h = __float2half_rn(v);
    g_Wh[(size_t)m * CCH * CCH + t] = h;
    g_Wl[(size_t)m * CCH * CCH + t] = __float2half_rn(v - __half2float(h));
}

// ---------------------------------------------------------------------------
// attn_logits (unchanged, known correct)
// ---------------------------------------------------------------------------
__global__ void __launch_bounds__(256) attn_logits(
    const float* __restrict__ Q, const float* __restrict__ Kp,
    float* __restrict__ A)
{
    const int bd = blockIdx.x;
    const int b  = bd >> 6;
    const int d  = bd & 63;
    const float* Qb = Q  + (size_t)b * CCH * NPIX + (size_t)d * NPIX;
    const float* Kb = Kp + (size_t)b * CCH * NPIX + (size_t)d * NPIX;

    float acc[64];
    #pragma unroll
    for (int e = 0; e < 64; e++) acc[e] = 0.f;

    for (int n = threadIdx.x; n < NPIX; n += 256) {
        float q[8], k[8];
        #pragma unroll
        for (int h = 0; h < 8; h++) {
            q[h] = Qb[(size_t)h * HD * NPIX + n];
            k[h] = Kb[(size_t)h * HD * NPIX + n];
        }
        #pragma unroll
        for (int i = 0; i < 8; i++)
            #pragma unroll
            for (int j = 0; j < 8; j++)
                acc[i * 8 + j] += q[i] * k[j];
    }

    const int lane = threadIdx.x & 31;
    const int warp = threadIdx.x >> 5;
    __shared__ float red[8][64];
    #pragma unroll
    for (int e = 0; e < 64; e++) {
        float v = acc[e];
        #pragma unroll
        for (int o = 16; o; o >>= 1) v += __shfl_down_sync(0xffffffffu, v, o);
        if (lane == 0) red[warp][e] = v;
    }
    __syncthreads();

    __shared__ float L[64];
    if (threadIdx.x < 64) {
        float s = 0.f;
        #pragma unroll
        for (int w = 0; w < 8; w++) s += red[w][threadIdx.x];
        L[threadIdx.x] = s * 0.125f;
    }
    __syncthreads();

    if (threadIdx.x < 8) {
        const int h = threadIdx.x;
        float m = -INFINITY;
        #pragma unroll
        for (int j = 0; j < 8; j++) m = fmaxf(m, L[h * 8 + j]);
        float e[8], s = 0.f;
        #pragma unroll
        for (int j = 0; j < 8; j++) { e[j] = expf(L[h * 8 + j] - m); s += e[j]; }
        const float inv = 1.f / s;
        #pragma unroll
        for (int j = 0; j < 8; j++)
            A[(size_t)bd * 64 + h * 8 + j] = e[j] * inv;
    }
}

// ---------------------------------------------------------------------------
// mix: writes Y as fp16 hi/lo splits (fp32 math)
// ---------------------------------------------------------------------------
__global__ void __launch_bounds__(256) mix_kernel(
    const float* __restrict__ A, const float* __restrict__ V,
    const float* __restrict__ gamma)
{
    const int bd = blockIdx.y;
    const int b  = bd >> 6;
    const int d  = bd & 63;

    __shared__ float a[64];
    if (threadIdx.x < 64)
        a[threadIdx.x] = A[(size_t)bd * 64 + threadIdx.x] * gamma[0];
    __syncthreads();

    const int n = blockIdx.x * 256 + threadIdx.x;
    const size_t base = (size_t)b * CCH * NPIX + (size_t)d * NPIX + n;

    float v[8];
    #pragma unroll
    for (int h = 0; h < 8; h++) v[h] = V[base + (size_t)h * HD * NPIX];
    #pragma unroll
    for (int h = 0; h < 8; h++) {
        float y = 0.f;
        #pragma unroll
        for (int j = 0; j < 8; j++) y += a[h * 8 + j] * v[j];
        const __half hy = __float2half_rn(y);
        g_Yh[base + (size_t)h * HD * NPIX] = hy;
        g_Yl[base + (size_t)h * HD * NPIX] = __float2half_rn(y - __half2float(hy));
    }
}

// ---------------------------------------------------------------------------
extern "C" void kernel_launch(void* const* d_in, const int* in_sizes, int n_in,
                              void* d_out, int out_size)
{
    const float* x  = (const float*)d_in[0];
    const float* Wq = (const float*)d_in[1];
    const float* bq = (const float*)d_in[2];
    const float* Wk = (const float*)d_in[3];
    const float* bk = (const float*)d_in[4];
    const float* Wv = (const float*)d_in[5];
    const float* bv = (const float*)d_in[6];
    const float* Wo = (const float*)d_in[7];
    const float* bo = (const float*)d_in[8];
    const float* gm = (const float*)d_in[9];
    float* out = (float*)d_out;

    float *Qp, *Kp, *Vp, *Ap;
    __half *Wh, *Wl, *Xh, *Xl, *Yh, *Yl;
    cudaGetSymbolAddress((void**)&Qp, g_Q);
    cudaGetSymbolAddress((void**)&Kp, g_K);
    cudaGetSymbolAddress((void**)&Vp, g_V);
    cudaGetSymbolAddress((void**)&Ap, g_A);
    cudaGetSymbolAddress((void**)&Wh, g_Wh);
    cudaGetSymbolAddress((void**)&Wl, g_Wl);
    cudaGetSymbolAddress((void**)&Xh, g_Xh);
    cudaGetSymbolAddress((void**)&Xl, g_Xl);
    cudaGetSymbolAddress((void**)&Yh, g_Yh);
    cudaGetSymbolAddress((void**)&Yl, g_Yl);

    cudaFuncSetAttribute(hgemm<false>, cudaFuncAttributeMaxDynamicSharedMemorySize, SMEM_BYTES);
    cudaFuncSetAttribute(hgemm<true>,  cudaFuncAttributeMaxDynamicSharedMemorySize, SMEM_BYTES);

    prep_w<<<dim3(CCH * CCH / 256, 4), 256>>>(Wq, Wk, Wv, Wo);
    {
        const size_t total = (size_t)BATCH * CCH * NPIX;
        prep_x<<<(unsigned)(total / (256 * 8)), 256>>>(x, Xh, Xl);
    }

    const size_t WS = (size_t)CCH * CCH;
    dim3 gg(NPIX / 128, CCH / 128, BATCH);   // (32, 4, 8)
    hgemm<false><<<gg, 512, SMEM_BYTES>>>(Wh + 0 * WS, Wl + 0 * WS, Xh, Xl, bq, nullptr, Qp);
    hgemm<false><<<gg, 512, SMEM_BYTES>>>(Wh + 1 * WS, Wl + 1 * WS, Xh, Xl, bk, nullptr, Kp);
    hgemm<false><<<gg, 512, SMEM_BYTES>>>(Wh + 2 * WS, Wl + 2 * WS, Xh, Xl, bv, nullptr, Vp);

    attn_logits<<<BATCH * HD, 256>>>(Qp, Kp, Ap);

    dim3 gm2(NPIX / 256, BATCH * HD);
    mix_kernel<<<gm2, 256>>>(Ap, Vp, gm);    // -> g_Yh/g_Yl

    hgemm<true><<<gg, 512, SMEM_BYTES>>>(Wh + 3 * WS, Wl + 3 * WS, Yh, Yl, bo, x, out);
}

// round 6
// speedup vs baseline: 3.1716x; 1.3471x over previous
#include <cuda_runtime.h>
#include <cuda_fp16.h>
#include <math.h>
#include <stdint.h>

#define CCH   512
#define NPIX  4096
#define BATCH 8
#define HD    64

// ---------------- scratch (no allocations allowed) ----------------
__device__ float g_Q[(size_t)BATCH * CCH * NPIX];
__device__ float g_K[(size_t)BATCH * CCH * NPIX];
__device__ float g_V[(size_t)BATCH * CCH * NPIX];
__device__ float g_A[BATCH * HD * 8 * 8];
__device__ __half g_Wh[4 * CCH * CCH];
__device__ __half g_Wl[4 * CCH * CCH];
__device__ __half g_Xh[(size_t)BATCH * CCH * NPIX];   // x split hi
__device__ __half g_Xl[(size_t)BATCH * CCH * NPIX];   // x split lo
__device__ __half g_Yh[(size_t)BATCH * CCH * NPIX];   // y fp16 (single-pass path)

// ---------------- helpers ----------------
__device__ __forceinline__ uint32_t smem_u32(const void* p) {
    uint32_t a;
    asm("{ .reg .u64 t; cvta.to.shared.u64 t, %1; cvt.u32.u64 %0, t; }" : "=r"(a) : "l"(p));
    return a;
}
__device__ __forceinline__ void cpasync16(uint32_t dst, const void* src) {
    asm volatile("cp.async.cg.shared.global [%0], [%1], 16;" :: "r"(dst), "l"(src));
}
#define CP_COMMIT() asm volatile("cp.async.commit_group;" ::: "memory")
template<int N> __device__ __forceinline__ void cp_wait() {
    asm volatile("cp.async.wait_group %0;" :: "n"(N) : "memory");
}
__device__ __forceinline__ void ldsm4(uint32_t* r, uint32_t addr) {
    asm volatile("ldmatrix.sync.aligned.m8n8.x4.shared.b16 {%0,%1,%2,%3}, [%4];"
                 : "=r"(r[0]), "=r"(r[1]), "=r"(r[2]), "=r"(r[3]) : "r"(addr));
}
__device__ __forceinline__ void ldsm4t(uint32_t* r, uint32_t addr) {
    asm volatile("ldmatrix.sync.aligned.m8n8.x4.trans.shared.b16 {%0,%1,%2,%3}, [%4];"
                 : "=r"(r[0]), "=r"(r[1]), "=r"(r[2]), "=r"(r[3]) : "r"(addr));
}
__device__ __forceinline__ void mma16816(float* c, const uint32_t* a, uint32_t b0, uint32_t b1) {
    asm volatile("mma.sync.aligned.m16n8k16.row.col.f32.f16.f16.f32 "
                 "{%0,%1,%2,%3}, {%4,%5,%6,%7}, {%8,%9}, {%0,%1,%2,%3};"
                 : "+f"(c[0]), "+f"(c[1]), "+f"(c[2]), "+f"(c[3])
                 : "r"(a[0]), "r"(a[1]), "r"(a[2]), "r"(a[3]), "r"(b0), "r"(b1));
}

// SMEM per-matrix layout (halfs): A padded to 40 halfs/row, B to 136
#define A_ST 40
#define B_ST 136
#define A_MAT (128 * A_ST)              // 5120 halfs
#define B_MAT (32 * B_ST)               // 4352 halfs
#define NSTAGE 4
#define NCH 16

// FULL stage: Ah, Al, Bh, Bl.  LITE stage: Ah, Bh.
#define STG_FULL (2 * A_MAT + 2 * B_MAT)      // 18944 halfs
#define STG_LITE (A_MAT + B_MAT)              //  9472 halfs
#define SMEM_FULL (NSTAGE * STG_FULL * 2)     // 151552 B
#define SMEM_LITE (NSTAGE * STG_LITE * 2)     //  75776 B

// ---------------------------------------------------------------------------
// hgemm: out[b][m][n] = sum_k W[m][k] * X[b][k][n] + bias[m] (+ resid)
// FULL: double-fp16, 3 mma passes (Ah*Bh + Ah*Bl + Al*Bh).
// LITE: single fp16 pass (Ah*Bh) — used where the error path is gamma-damped.
// grid (NPIX/128, CCH/128, B), 512 threads (16 warps, 32x32 warp tiles)
// ---------------------------------------------------------------------------
template<bool RESID, bool FULL>
__global__ void __launch_bounds__(512, 1) hgemm(
    const __half* __restrict__ Whg, const __half* __restrict__ Wlg,
    const __half* __restrict__ Xhg, const __half* __restrict__ Xlg,
    const float* __restrict__ bias, const float* __restrict__ resid,
    float* __restrict__ out)
{
    extern __shared__ __half sm[];
    const uint32_t sb = smem_u32(sm);

    constexpr int STG    = FULL ? STG_FULL : STG_LITE;
    constexpr int OFF_AH = 0;
    constexpr int OFF_AL = A_MAT;                       // FULL only
    constexpr int OFF_BH = FULL ? 2 * A_MAT : A_MAT;
    constexpr int OFF_BL = 2 * A_MAT + B_MAT;           // FULL only

    const int tid = threadIdx.x;
    const int lane = tid & 31, wid = tid >> 5;
    const int wm = wid >> 2, wn = wid & 3;
    const int b = blockIdx.z;
    const int m0 = blockIdx.y * 128, n0 = blockIdx.x * 128;
    const __half* Bhp = Xhg + (size_t)b * CCH * NPIX;
    const __half* Blp = FULL ? (Xlg + (size_t)b * CCH * NPIX) : nullptr;

    const int ar = tid >> 2, ak = (tid & 3) * 8;
    const int br = tid >> 4, bn = (tid & 15) * 8;

    const int quad = lane >> 3, r8 = lane & 7;
    const int qlow = (quad & 1) * 8, qhi = (quad >> 1) * 8;

    float c[2][4][4];
    #pragma unroll
    for (int i = 0; i < 2; i++)
        #pragma unroll
        for (int j = 0; j < 4; j++)
            #pragma unroll
            for (int e = 0; e < 4; e++) c[i][j][e] = 0.f;

    auto issue = [&](int s, int ch) {
        const int k0 = ch * 32;
        const uint32_t st = sb + 2 * (s * STG);
        cpasync16(st + 2 * (OFF_AH + ar * A_ST + ak),
                  Whg + (size_t)(m0 + ar) * CCH + k0 + ak);
        cpasync16(st + 2 * (OFF_BH + br * B_ST + bn),
                  Bhp + (size_t)(k0 + br) * NPIX + n0 + bn);
        if (FULL) {
            cpasync16(st + 2 * (OFF_AL + ar * A_ST + ak),
                      Wlg + (size_t)(m0 + ar) * CCH + k0 + ak);
            cpasync16(st + 2 * (OFF_BL + br * B_ST + bn),
                      Blp + (size_t)(k0 + br) * NPIX + n0 + bn);
        }
    };

    issue(0, 0); CP_COMMIT();
    issue(1, 1); CP_COMMIT();

    for (int ch = 0; ch < NCH; ch++) {
        const int s = ch & 3;
        if (ch + 2 < NCH) { issue((ch + 2) & 3, ch + 2); CP_COMMIT(); }
        if (ch + 2 < NCH)      cp_wait<2>();
        else if (ch + 1 < NCH) cp_wait<1>();
        else                   cp_wait<0>();
        __syncthreads();

        const uint32_t sbase = sb + 2 * (s * STG);
        #pragma unroll
        for (int k16 = 0; k16 < 2; k16++) {
            uint32_t ah[2][4], al[2][4], bh[2][4], bl[2][4];
            #pragma unroll
            for (int mi = 0; mi < 2; mi++) {
                const uint32_t off = 2 * ((uint32_t)(wm * 32 + mi * 16 + r8 + qlow) * A_ST
                                          + k16 * 16 + qhi);
                ldsm4(ah[mi], sbase + 2 * OFF_AH + off);
                if (FULL) ldsm4(al[mi], sbase + 2 * OFF_AL + off);
            }
            #pragma unroll
            for (int ni = 0; ni < 2; ni++) {
                const uint32_t off = 2 * ((uint32_t)(k16 * 16 + r8 + qlow) * B_ST
                                          + wn * 32 + ni * 16 + qhi);
                ldsm4t(bh[ni], sbase + 2 * OFF_BH + off);
                if (FULL) ldsm4t(bl[ni], sbase + 2 * OFF_BL + off);
            }
            #pragma unroll
            for (int mi = 0; mi < 2; mi++)
                #pragma unroll
                for (int j = 0; j < 4; j++) {
                    const int ni = j >> 1, ss = (j & 1) * 2;
                    mma16816(c[mi][j], ah[mi], bh[ni][ss], bh[ni][ss + 1]);
                    if (FULL) {
                        mma16816(c[mi][j], ah[mi], bl[ni][ss], bl[ni][ss + 1]);
                        mma16816(c[mi][j], al[mi], bh[ni][ss], bh[ni][ss + 1]);
                    }
                }
        }
        __syncthreads();
    }

    // epilogue
    #pragma unroll
    for (int mi = 0; mi < 2; mi++) {
        #pragma unroll
        for (int rr = 0; rr < 2; rr++) {
            const int m = m0 + wm * 32 + mi * 16 + (lane >> 2) + rr * 8;
            const float bi = __ldg(&bias[m]);
            const size_t rowoff = ((size_t)b * CCH + m) * NPIX + n0 + wn * 32 + (lane & 3) * 2;
            #pragma unroll
            for (int j = 0; j < 4; j++) {
                float2 v;
                v.x = c[mi][j][rr * 2 + 0] + bi;
                v.y = c[mi][j][rr * 2 + 1] + bi;
                if (RESID) {
                    float2 r = *(const float2*)&resid[rowoff + j * 8];
                    v.x += r.x; v.y += r.y;
                }
                *(float2*)&out[rowoff + j * 8] = v;
            }
        }
    }
}

// ---------------------------------------------------------------------------
__global__ void __launch_bounds__(256) prep_x(
    const float* __restrict__ src, __half* __restrict__ hi, __half* __restrict__ lo)
{
    const size_t i = ((size_t)blockIdx.x * 256 + threadIdx.x) * 8;
    float4 v0 = *(const float4*)&src[i];
    float4 v1 = *(const float4*)&src[i + 4];
    const float v[8] = {v0.x, v0.y, v0.z, v0.w, v1.x, v1.y, v1.z, v1.w};
    __half h[8], l[8];
    #pragma unroll
    for (int e = 0; e < 8; e++) {
        h[e] = __float2half_rn(v[e]);
        l[e] = __float2half_rn(v[e] - __half2float(h[e]));
    }
    *(uint4*)&hi[i] = *(const uint4*)h;
    *(uint4*)&lo[i] = *(const uint4*)l;
}

__global__ void __launch_bounds__(256) prep_w(
    const float* __restrict__ Wq, const float* __restrict__ Wk,
    const float* __restrict__ Wv, const float* __restrict__ Wo)
{
    const int m = blockIdx.y;
    const size_t t = (size_t)blockIdx.x * 256 + threadIdx.x;
    const float* W = (m == 0) ? Wq : (m == 1) ? Wk : (m == 2) ? Wv : Wo;
    const float v = W[t];
    const __half h = __float2half_rn(v);
    g_Wh[(size_t)m * CCH * CCH + t] = h;
    g_Wl[(size_t)m * CCH * CCH + t] = __float2half_rn(v - __half2float(h));
}

// ---------------------------------------------------------------------------
__global__ void __launch_bounds__(256) attn_logits(
    const float* __restrict__ Q, const float* __restrict__ Kp,
    float* __restrict__ A)
{
    const int bd = blockIdx.x;
    const int b  = bd >> 6;
    const int d  = bd & 63;
    const float* Qb = Q  + (size_t)b * CCH * NPIX + (size_t)d * NPIX;
    const float* Kb = Kp + (size_t)b * CCH * NPIX + (size_t)d * NPIX;

    float acc[64];
    #pragma unroll
    for (int e = 0; e < 64; e++) acc[e] = 0.f;

    for (int n = threadIdx.x; n < NPIX; n += 256) {
        float q[8], k[8];
        #pragma unroll
        for (int h = 0; h < 8; h++) {
            q[h] = Qb[(size_t)h * HD * NPIX + n];
            k[h] = Kb[(size_t)h * HD * NPIX + n];
        }
        #pragma unroll
        for (int i = 0; i < 8; i++)
            #pragma unroll
            for (int j = 0; j < 8; j++)
                acc[i * 8 + j] += q[i] * k[j];
    }

    const int lane = threadIdx.x & 31;
    const int warp = threadIdx.x >> 5;
    __shared__ float red[8][64];
    #pragma unroll
    for (int e = 0; e < 64; e++) {
        float v = acc[e];
        #pragma unroll
        for (int o = 16; o; o >>= 1) v += __shfl_down_sync(0xffffffffu, v, o);
        if (lane == 0) red[warp][e] = v;
    }
    __syncthreads();

    __shared__ float L[64];
    if (threadIdx.x < 64) {
        float s = 0.f;
        #pragma unroll
        for (int w = 0; w < 8; w++) s += red[w][threadIdx.x];
        L[threadIdx.x] = s * 0.125f;
    }
    __syncthreads();

    if (threadIdx.x < 8) {
        const int h = threadIdx.x;
        float m = -INFINITY;
        #pragma unroll
        for (int j = 0; j < 8; j++) m = fmaxf(m, L[h * 8 + j]);
        float e[8], s = 0.f;
        #pragma unroll
        for (int j = 0; j < 8; j++) { e[j] = expf(L[h * 8 + j] - m); s += e[j]; }
        const float inv = 1.f / s;
        #pragma unroll
        for (int j = 0; j < 8; j++)
            A[(size_t)bd * 64 + h * 8 + j] = e[j] * inv;
    }
}

// ---------------------------------------------------------------------------
// mix: fp32 math, writes Y as fp16 (single-pass output path)
// ---------------------------------------------------------------------------
__global__ void __launch_bounds__(256) mix_kernel(
    const float* __restrict__ A, const float* __restrict__ V,
    const float* __restrict__ gamma)
{
    const int bd = blockIdx.y;
    const int b  = bd >> 6;
    const int d  = bd & 63;

    __shared__ float a[64];
    if (threadIdx.x < 64)
        a[threadIdx.x] = A[(size_t)bd * 64 + threadIdx.x] * gamma[0];
    __syncthreads();

    const int n = blockIdx.x * 256 + threadIdx.x;
    const size_t base = (size_t)b * CCH * NPIX + (size_t)d * NPIX + n;

    float v[8];
    #pragma unroll
    for (int h = 0; h < 8; h++) v[h] = V[base + (size_t)h * HD * NPIX];
    #pragma unroll
    for (int h = 0; h < 8; h++) {
        float y = 0.f;
        #pragma unroll
        for (int j = 0; j < 8; j++) y += a[h * 8 + j] * v[j];
        g_Yh[base + (size_t)h * HD * NPIX] = __float2half_rn(y);
    }
}

// ---------------------------------------------------------------------------
extern "C" void kernel_launch(void* const* d_in, const int* in_sizes, int n_in,
                              void* d_out, int out_size)
{
    const float* x  = (const float*)d_in[0];
    const float* Wq = (const float*)d_in[1];
    const float* bq = (const float*)d_in[2];
    const float* Wk = (const float*)d_in[3];
    const float* bk = (const float*)d_in[4];
    const float* Wv = (const float*)d_in[5];
    const float* bv = (const float*)d_in[6];
    const float* Wo = (const float*)d_in[7];
    const float* bo = (const float*)d_in[8];
    const float* gm = (const float*)d_in[9];
    float* out = (float*)d_out;

    float *Qp, *Kp, *Vp, *Ap;
    __half *Wh, *Wl, *Xh, *Xl, *Yh;
    cudaGetSymbolAddress((void**)&Qp, g_Q);
    cudaGetSymbolAddress((void**)&Kp, g_K);
    cudaGetSymbolAddress((void**)&Vp, g_V);
    cudaGetSymbolAddress((void**)&Ap, g_A);
    cudaGetSymbolAddress((void**)&Wh, g_Wh);
    cudaGetSymbolAddress((void**)&Wl, g_Wl);
    cudaGetSymbolAddress((void**)&Xh, g_Xh);
    cudaGetSymbolAddress((void**)&Xl, g_Xl);
    cudaGetSymbolAddress((void**)&Yh, g_Yh);

    cudaFuncSetAttribute(hgemm<false, true>,  cudaFuncAttributeMaxDynamicSharedMemorySize, SMEM_FULL);
    cudaFuncSetAttribute(hgemm<false, false>, cudaFuncAttributeMaxDynamicSharedMemorySize, SMEM_LITE);
    cudaFuncSetAttribute(hgemm<true,  false>, cudaFuncAttributeMaxDynamicSharedMemorySize, SMEM_LITE);

    prep_w<<<dim3(CCH * CCH / 256, 4), 256>>>(Wq, Wk, Wv, Wo);
    {
        const size_t total = (size_t)BATCH * CCH * NPIX;
        prep_x<<<(unsigned)(total / (256 * 8)), 256>>>(x, Xh, Xl);
    }

    const size_t WS = (size_t)CCH * CCH;
    dim3 gg(NPIX / 128, CCH / 128, BATCH);   // (32, 4, 8)
    // Q, K: precision-critical (feed softmax) -> 3-pass
    hgemm<false, true><<<gg, 512, SMEM_FULL>>>(Wh + 0 * WS, Wl + 0 * WS, Xh, Xl, bq, nullptr, Qp);
    hgemm<false, true><<<gg, 512, SMEM_FULL>>>(Wh + 1 * WS, Wl + 1 * WS, Xh, Xl, bk, nullptr, Kp);
    // V: gamma-damped linear path -> 1-pass
    hgemm<false, false><<<gg, 512, SMEM_LITE>>>(Wh + 2 * WS, nullptr, Xh, nullptr, bv, nullptr, Vp);

    attn_logits<<<BATCH * HD, 256>>>(Qp, Kp, Ap);

    dim3 gm2(NPIX / 256, BATCH * HD);
    mix_kernel<<<gm2, 256>>>(Ap, Vp, gm);    // -> g_Yh (fp16)

    // Output projection: gamma-damped -> 1-pass
    hgemm<true, false><<<gg, 512, SMEM_LITE>>>(Wh + 3 * WS, nullptr, Yh, nullptr, bo, x, out);
}

// round 7
// speedup vs baseline: 4.6379x; 1.4623x over previous
#include <cuda_runtime.h>
#include <cuda_fp16.h>
#include <math.h>
#include <stdint.h>

#define CCH   512
#define NPIX  4096
#define BATCH 8

// ---------------- scratch ----------------
__device__ __half g_Xh[(size_t)BATCH * CCH * NPIX];
__device__ __half g_Xl[(size_t)BATCH * CCH * NPIX];
__device__ __half g_XTh[(size_t)BATCH * CCH * NPIX];
__device__ __half g_XTl[(size_t)BATCH * CCH * NPIX];
__device__ __half g_Wh[4 * CCH * CCH];
__device__ __half g_Wl[4 * CCH * CCH];
__device__ float  g_s [BATCH * CCH];
__device__ float  g_qs[BATCH * CCH];
__device__ float  g_ks[BATCH * CCH];
__device__ float  g_by[BATCH * CCH];
__device__ float  g_bo2[BATCH * CCH];
__device__ float  g_Gp[4][(size_t)BATCH * CCH * CCH];   // split-K partials
__device__ __half g_Gh[(size_t)BATCH * CCH * CCH];
__device__ __half g_Gl[(size_t)BATCH * CCH * CCH];
__device__ float  g_U [(size_t)BATCH * CCH * CCH];
__device__ float  g_A [BATCH * 64 * 64];                // gamma-folded softmax
__device__ __half g_Wyh[(size_t)BATCH * CCH * CCH];
__device__ float  g_M [(size_t)BATCH * CCH * CCH];
__device__ __half g_Mh[(size_t)BATCH * CCH * CCH];

__constant__ int c_pm[10] = {0,0,0,0,1,1,1,2,2,3};
__constant__ int c_pn[10] = {0,1,2,3,1,2,3,2,3,3};

// ---------------- helpers ----------------
__device__ __forceinline__ uint32_t smem_u32(const void* p) {
    uint32_t a;
    asm("{ .reg .u64 t; cvta.to.shared.u64 t, %1; cvt.u32.u64 %0, t; }" : "=r"(a) : "l"(p));
    return a;
}
__device__ __forceinline__ void cpasync16(uint32_t dst, const void* src) {
    asm volatile("cp.async.cg.shared.global [%0], [%1], 16;" :: "r"(dst), "l"(src));
}
#define CP_COMMIT() asm volatile("cp.async.commit_group;" ::: "memory")
template<int N> __device__ __forceinline__ void cp_wait() {
    asm volatile("cp.async.wait_group %0;" :: "n"(N) : "memory");
}
__device__ __forceinline__ void ldsm4(uint32_t* r, uint32_t addr) {
    asm volatile("ldmatrix.sync.aligned.m8n8.x4.shared.b16 {%0,%1,%2,%3}, [%4];"
                 : "=r"(r[0]), "=r"(r[1]), "=r"(r[2]), "=r"(r[3]) : "r"(addr));
}
__device__ __forceinline__ void ldsm4t(uint32_t* r, uint32_t addr) {
    asm volatile("ldmatrix.sync.aligned.m8n8.x4.trans.shared.b16 {%0,%1,%2,%3}, [%4];"
                 : "=r"(r[0]), "=r"(r[1]), "=r"(r[2]), "=r"(r[3]) : "r"(addr));
}
__device__ __forceinline__ void mma16816(float* c, const uint32_t* a, uint32_t b0, uint32_t b1) {
    asm volatile("mma.sync.aligned.m16n8k16.row.col.f32.f16.f16.f32 "
                 "{%0,%1,%2,%3}, {%4,%5,%6,%7}, {%8,%9}, {%0,%1,%2,%3};"
                 : "+f"(c[0]), "+f"(c[1]), "+f"(c[2]), "+f"(c[3])
                 : "r"(a[0]), "r"(a[1]), "r"(a[2]), "r"(a[3]), "r"(b0), "r"(b1));
}

#define A_ST 40
#define B_ST 136
#define A_MAT (128 * A_ST)
#define B_MAT (32 * B_ST)
#define STG_FULL (2 * A_MAT + 2 * B_MAT)
#define STG_LITE (A_MAT + B_MAT)
#define SMEM_FULL (4 * STG_FULL * 2)
#define SMEM_LITE (4 * STG_LITE * 2)

// ---------------------------------------------------------------------------
// hgemm: out[b][m][n] = sum_k W[m,k] * X[b][k][n] (+bias[b][m]) (+resid)
// Generic: runtime npix/kfull/nch, batched W via wstride, split-K via z,
// upper-triangle tile remap via TRI (for the symmetric Gram product).
// ---------------------------------------------------------------------------
template<bool RESID, bool FULL, bool TRI>
__global__ void __launch_bounds__(512, 1) hgemm(
    const __half* __restrict__ Whg, const __half* __restrict__ Wlg,
    const __half* __restrict__ Xhg, const __half* __restrict__ Xlg,
    const float* __restrict__ bias, const float* __restrict__ resid,
    float* __restrict__ out,
    int npix, int kfull, int nch,
    size_t wstride, size_t xstride, int bstride, size_t oslice)
{
    extern __shared__ __half sm[];
    const uint32_t sb = smem_u32(sm);
    constexpr int STG = FULL ? STG_FULL : STG_LITE;
    constexpr int OFF_AH = 0, OFF_AL = A_MAT;
    constexpr int OFF_BH = FULL ? 2 * A_MAT : A_MAT;
    constexpr int OFF_BL = 2 * A_MAT + B_MAT;

    const int tid = threadIdx.x, lane = tid & 31, wid = tid >> 5;
    const int wm = wid >> 2, wn = wid & 3;
    const int b = blockIdx.z & 7, ksl = blockIdx.z >> 3;
    const int m0 = (TRI ? c_pm[blockIdx.x] : (int)blockIdx.y) * 128;
    const int n0 = (TRI ? c_pn[blockIdx.x] : (int)blockIdx.x) * 128;
    const int kg0 = ksl * nch * 32;
    const __half* Wb  = Whg + (size_t)b * wstride;
    const __half* Wlb = FULL ? Wlg + (size_t)b * wstride : nullptr;
    const __half* Bhp = Xhg + (size_t)b * xstride;
    const __half* Blp = FULL ? Xlg + (size_t)b * xstride : nullptr;
    float* outp = out + ksl * oslice;

    const int ar = tid >> 2, ak = (tid & 3) * 8;
    const int br = tid >> 4, bn = (tid & 15) * 8;
    const int quad = lane >> 3, r8 = lane & 7;
    const int qlow = (quad & 1) * 8, qhi = (quad >> 1) * 8;

    float c[2][4][4];
    #pragma unroll
    for (int i = 0; i < 2; i++)
        #pragma unroll
        for (int j = 0; j < 4; j++)
            #pragma unroll
            for (int e = 0; e < 4; e++) c[i][j][e] = 0.f;

    auto issue = [&](int s, int ch) {
        const int k0 = kg0 + ch * 32;
        const uint32_t st = sb + 2 * (s * STG);
        cpasync16(st + 2 * (OFF_AH + ar * A_ST + ak), Wb  + (size_t)(m0 + ar) * kfull + k0 + ak);
        cpasync16(st + 2 * (OFF_BH + br * B_ST + bn), Bhp + (size_t)(k0 + br) * npix + n0 + bn);
        if (FULL) {
            cpasync16(st + 2 * (OFF_AL + ar * A_ST + ak), Wlb + (size_t)(m0 + ar) * kfull + k0 + ak);
            cpasync16(st + 2 * (OFF_BL + br * B_ST + bn), Blp + (size_t)(k0 + br) * npix + n0 + bn);
        }
    };

    issue(0, 0); CP_COMMIT();
    issue(1, 1); CP_COMMIT();

    for (int ch = 0; ch < nch; ch++) {
        const int s = ch & 3;
        if (ch + 2 < nch) { issue((ch + 2) & 3, ch + 2); CP_COMMIT(); }
        if (ch + 2 < nch)      cp_wait<2>();
        else if (ch + 1 < nch) cp_wait<1>();
        else                   cp_wait<0>();
        __syncthreads();

        const uint32_t sbase = sb + 2 * (s * STG);
        #pragma unroll
        for (int k16 = 0; k16 < 2; k16++) {
            uint32_t ah[2][4], al[2][4], bh[2][4], bl[2][4];
            #pragma unroll
            for (int mi = 0; mi < 2; mi++) {
                const uint32_t off = 2 * ((uint32_t)(wm * 32 + mi * 16 + r8 + qlow) * A_ST + k16 * 16 + qhi);
                ldsm4(ah[mi], sbase + 2 * OFF_AH + off);
                if (FULL) ldsm4(al[mi], sbase + 2 * OFF_AL + off);
            }
            #pragma unroll
            for (int ni = 0; ni < 2; ni++) {
                const uint32_t off = 2 * ((uint32_t)(k16 * 16 + r8 + qlow) * B_ST + wn * 32 + ni * 16 + qhi);
                ldsm4t(bh[ni], sbase + 2 * OFF_BH + off);
                if (FULL) ldsm4t(bl[ni], sbase + 2 * OFF_BL + off);
            }
            #pragma unroll
            for (int mi = 0; mi < 2; mi++)
                #pragma unroll
                for (int j = 0; j < 4; j++) {
                    const int ni = j >> 1, ss = (j & 1) * 2;
                    mma16816(c[mi][j], ah[mi], bh[ni][ss], bh[ni][ss + 1]);
                    if (FULL) {
                        mma16816(c[mi][j], ah[mi], bl[ni][ss], bl[ni][ss + 1]);
                        mma16816(c[mi][j], al[mi], bh[ni][ss], bh[ni][ss + 1]);
                    }
                }
        }
        __syncthreads();
    }

    #pragma unroll
    for (int mi = 0; mi < 2; mi++) {
        #pragma unroll
        for (int rr = 0; rr < 2; rr++) {
            const int m = m0 + wm * 32 + mi * 16 + (lane >> 2) + rr * 8;
            const float bi = bias ? __ldg(&bias[b * bstride + m]) : 0.f;
            const size_t rowoff = ((size_t)b * CCH + m) * npix + n0 + wn * 32 + (lane & 3) * 2;
            #pragma unroll
            for (int j = 0; j < 4; j++) {
                float2 v;
                v.x = c[mi][j][rr * 2 + 0] + bi;
                v.y = c[mi][j][rr * 2 + 1] + bi;
                if (RESID) {
                    float2 r = *(const float2*)&resid[rowoff + j * 8];
                    v.x += r.x; v.y += r.y;
                }
                *(float2*)&outp[rowoff + j * 8] = v;
            }
        }
    }
}

// ---------------------------------------------------------------------------
__global__ void zero_s() { g_s[blockIdx.x * 512 + threadIdx.x] = 0.f; }

// split x -> Xh/Xl and accumulate s[b][c] = sum_n x (block covers 2048 elems of one row)
__global__ void __launch_bounds__(256) prep_x(const float* __restrict__ src) {
    __shared__ float red[256];
    const size_t i = ((size_t)blockIdx.x * 256 + threadIdx.x) * 8;
    float4 v0 = *(const float4*)&src[i];
    float4 v1 = *(const float4*)&src[i + 4];
    const float v[8] = {v0.x, v0.y, v0.z, v0.w, v1.x, v1.y, v1.z, v1.w};
    __half h[8], l[8];
    float ps = 0.f;
    #pragma unroll
    for (int e = 0; e < 8; e++) {
        h[e] = __float2half_rn(v[e]);
        l[e] = __float2half_rn(v[e] - __half2float(h[e]));
        ps += v[e];
    }
    *(uint4*)&g_Xh[i] = *(const uint4*)h;
    *(uint4*)&g_Xl[i] = *(const uint4*)l;
    red[threadIdx.x] = ps; __syncthreads();
    for (int o = 128; o; o >>= 1) {
        if (threadIdx.x < o) red[threadIdx.x] += red[threadIdx.x + o];
        __syncthreads();
    }
    if (threadIdx.x == 0) atomicAdd(&g_s[blockIdx.x >> 1], red[0]);
}

// transpose + split: x[b][c][n] -> XT[b][n][c]
__global__ void __launch_bounds__(256) prep_xT(const float* __restrict__ x) {
    __shared__ float s[32][33];
    const int n0 = blockIdx.x * 32, c0 = blockIdx.y * 32, b = blockIdx.z;
    const int tx = threadIdx.x, ty = threadIdx.y;
    #pragma unroll
    for (int i = 0; i < 4; i++)
        s[ty + 8 * i][tx] = x[((size_t)(b * CCH + c0 + ty + 8 * i)) * NPIX + n0 + tx];
    __syncthreads();
    #pragma unroll
    for (int i = 0; i < 4; i++) {
        const float v = s[tx][ty + 8 * i];
        const __half hi = __float2half_rn(v);
        const size_t idx = ((size_t)b * NPIX + n0 + ty + 8 * i) * CCH + c0 + tx;
        g_XTh[idx] = hi;
        g_XTl[idx] = __float2half_rn(v - __half2float(hi));
    }
}

__global__ void __launch_bounds__(256) prep_w(
    const float* __restrict__ Wq, const float* __restrict__ Wk,
    const float* __restrict__ Wv, const float* __restrict__ Wo)
{
    const int m = blockIdx.y;
    const size_t t = (size_t)blockIdx.x * 256 + threadIdx.x;
    const float* W = (m == 0) ? Wq : (m == 1) ? Wk : (m == 2) ? Wv : Wo;
    const float v = W[t];
    const __half h = __float2half_rn(v);
    g_Wh[(size_t)m * CCH * CCH + t] = h;
    g_Wl[(size_t)m * CCH * CCH + t] = __float2half_rn(v - __half2float(h));
}

// sum 4 split-K partials, mirror lower triangle, split to fp16
__global__ void __launch_bounds__(256) splitG() {
    __shared__ float s[32][33];
    const int ti = blockIdx.x, tj = blockIdx.y, b = blockIdx.z;
    const int tx = threadIdx.x, ty = threadIdx.y;
    const size_t base = (size_t)b * CCH * CCH;
    const bool swap = (ti >> 2) > (tj >> 2);
    if (!swap) {
        #pragma unroll
        for (int k = 0; k < 4; k++) {
            const int r = ti * 32 + ty + 8 * k, cc = tj * 32 + tx;
            const size_t o = base + (size_t)r * CCH + cc;
            float v = g_Gp[0][o] + g_Gp[1][o] + g_Gp[2][o] + g_Gp[3][o];
            const __half hi = __float2half_rn(v);
            g_Gh[o] = hi; g_Gl[o] = __float2half_rn(v - __half2float(hi));
        }
    } else {
        #pragma unroll
        for (int k = 0; k < 4; k++) {
            const int r = tj * 32 + ty + 8 * k, cc = ti * 32 + tx;
            const size_t o = base + (size_t)r * CCH + cc;
            s[ty + 8 * k][tx] = g_Gp[0][o] + g_Gp[1][o] + g_Gp[2][o] + g_Gp[3][o];
        }
        __syncthreads();
        #pragma unroll
        for (int k = 0; k < 4; k++) {
            const int r = ti * 32 + ty + 8 * k, cc = tj * 32 + tx;
            const float v = s[tx][ty + 8 * k];
            const __half hi = __float2half_rn(v);
            const size_t o = base + (size_t)r * CCH + cc;
            g_Gh[o] = hi; g_Gl[o] = __float2half_rn(v - __half2float(hi));
        }
    }
}

// o[b][m] = sum_k W[m,k]*v[b,k] (+ add[m])
__global__ void __launch_bounds__(256) gemv(
    const float* __restrict__ W, const float* __restrict__ v,
    const float* __restrict__ add, float* __restrict__ o)
{
    const int b = blockIdx.y, m = blockIdx.x * 8 + (threadIdx.x >> 5), lane = threadIdx.x & 31;
    const float* vb = v + b * 512;
    float acc = 0.f;
    for (int k = lane; k < 512; k += 32) acc += W[(size_t)m * 512 + k] * vb[k];
    #pragma unroll
    for (int off = 16; off; off >>= 1) acc += __shfl_down_sync(0xffffffffu, acc, off);
    if (lane == 0) o[b * 512 + m] = acc + (add ? add[m] : 0.f);
}

// L[h][h'] = (sum_c U[hd,c]*Wk[h'd,c] + bias terms)/8, softmax, *gamma
__global__ void __launch_bounds__(256) lsoftmax(
    const float* __restrict__ Wk, const float* __restrict__ bq,
    const float* __restrict__ bk, const float* __restrict__ gamma)
{
    const int d = blockIdx.x, b = blockIdx.y;
    const int t = threadIdx.x, pair = t >> 2, h = pair >> 3, hp = pair & 7, cs = t & 3;
    const float* Ur = g_U + ((size_t)b * 512 + h * 64 + d) * 512;
    const float* Kr = Wk + (size_t)(hp * 64 + d) * 512;
    float acc = 0.f;
    for (int cc = cs; cc < 512; cc += 4) acc += Ur[cc] * Kr[cc];
    acc += __shfl_down_sync(0xffffffffu, acc, 2);
    acc += __shfl_down_sync(0xffffffffu, acc, 1);
    __shared__ float sL[64];
    if (cs == 0) {
        const int qi = h * 64 + d, ki = hp * 64 + d;
        const float Lv = acc + bq[qi] * g_ks[b * 512 + ki] + bk[ki] * g_qs[b * 512 + qi]
                       + 4096.f * bq[qi] * bk[ki];
        sL[pair] = Lv * 0.125f;
    }
    __syncthreads();
    if (t < 8) {
        float m = -INFINITY;
        #pragma unroll
        for (int j = 0; j < 8; j++) m = fmaxf(m, sL[t * 8 + j]);
        float e[8], ssum = 0.f;
        #pragma unroll
        for (int j = 0; j < 8; j++) { e[j] = expf(sL[t * 8 + j] - m); ssum += e[j]; }
        const float sc = gamma[0] / ssum;
        #pragma unroll
        for (int j = 0; j < 8; j++) g_A[b * 4096 + d * 64 + t * 8 + j] = e[j] * sc;
    }
}

// Wy[b][h*64+d][c] = sum_j (gA)[d,h,j]*Wv[j*64+d][c]; by = sum_j (gA)*bv
__global__ void __launch_bounds__(256) build_wy(
    const float* __restrict__ Wv, const float* __restrict__ bv)
{
    const int d = blockIdx.x, b = blockIdx.y, t = threadIdx.x;
    __shared__ float a[64];
    if (t < 64) a[t] = g_A[b * 4096 + d * 64 + t];
    __syncthreads();
    if (t < 8) {
        float s = 0.f;
        #pragma unroll
        for (int j = 0; j < 8; j++) s += a[t * 8 + j] * bv[j * 64 + d];
        g_by[b * 512 + t * 64 + d] = s;
    }
    for (int cc = t; cc < 512; cc += 256) {
        float v[8];
        #pragma unroll
        for (int j = 0; j < 8; j++) v[j] = Wv[(size_t)(j * 64 + d) * 512 + cc];
        #pragma unroll
        for (int hh = 0; hh < 8; hh++) {
            float y = 0.f;
            #pragma unroll
            for (int j = 0; j < 8; j++) y += a[hh * 8 + j] * v[j];
            g_Wyh[(size_t)b * CCH * CCH + (size_t)(hh * 64 + d) * 512 + cc] = __float2half_rn(y);
        }
    }
}

__global__ void __launch_bounds__(256) to_half(const float* __restrict__ src, __half* __restrict__ dst) {
    const size_t i = ((size_t)blockIdx.x * 256 + threadIdx.x) * 4;
    float4 v = *(const float4*)&src[i];
    __half h[4] = {__float2half_rn(v.x), __float2half_rn(v.y),
                   __float2half_rn(v.z), __float2half_rn(v.w)};
    *(uint2*)&dst[i] = *(const uint2*)h;
}

// ---------------------------------------------------------------------------
extern "C" void kernel_launch(void* const* d_in, const int* in_sizes, int n_in,
                              void* d_out, int out_size)
{
    const float* x  = (const float*)d_in[0];
    const float* Wq = (const float*)d_in[1];
    const float* bq = (const float*)d_in[2];
    const float* Wk = (const float*)d_in[3];
    const float* bk = (const float*)d_in[4];
    const float* Wv = (const float*)d_in[5];
    const float* bv = (const float*)d_in[6];
    const float* Wo = (const float*)d_in[7];
    const float* bo = (const float*)d_in[8];
    const float* gm = (const float*)d_in[9];
    float* out = (float*)d_out;

    __half *Xh, *Xl, *XTh, *XTl, *Wh, *Wl, *Gh, *Gl, *Wyh, *Mh;
    float *sP, *qsP, *ksP, *byP, *boP, *GpP, *UP, *MP;
    cudaGetSymbolAddress((void**)&Xh, g_Xh);   cudaGetSymbolAddress((void**)&Xl, g_Xl);
    cudaGetSymbolAddress((void**)&XTh, g_XTh); cudaGetSymbolAddress((void**)&XTl, g_XTl);
    cudaGetSymbolAddress((void**)&Wh, g_Wh);   cudaGetSymbolAddress((void**)&Wl, g_Wl);
    cudaGetSymbolAddress((void**)&Gh, g_Gh);   cudaGetSymbolAddress((void**)&Gl, g_Gl);
    cudaGetSymbolAddress((void**)&Wyh, g_Wyh); cudaGetSymbolAddress((void**)&Mh, g_Mh);
    cudaGetSymbolAddress((void**)&sP, g_s);    cudaGetSymbolAddress((void**)&qsP, g_qs);
    cudaGetSymbolAddress((void**)&ksP, g_ks);  cudaGetSymbolAddress((void**)&byP, g_by);
    cudaGetSymbolAddress((void**)&boP, g_bo2); cudaGetSymbolAddress((void**)&GpP, g_Gp);
    cudaGetSymbolAddress((void**)&UP, g_U);    cudaGetSymbolAddress((void**)&MP, g_M);

    static bool attr = false;
    if (!attr) {
        cudaFuncSetAttribute(hgemm<false, true,  true >, cudaFuncAttributeMaxDynamicSharedMemorySize, SMEM_FULL);
        cudaFuncSetAttribute(hgemm<false, true,  false>, cudaFuncAttributeMaxDynamicSharedMemorySize, SMEM_FULL);
        cudaFuncSetAttribute(hgemm<false, false, false>, cudaFuncAttributeMaxDynamicSharedMemorySize, SMEM_LITE);
        cudaFuncSetAttribute(hgemm<true,  false, false>, cudaFuncAttributeMaxDynamicSharedMemorySize, SMEM_LITE);
        attr = true;
    }

    const size_t WS = (size_t)CCH * CCH;
    const size_t XS = (size_t)CCH * NPIX;

    zero_s<<<8, 512>>>();
    prep_x<<<(unsigned)((size_t)BATCH * XS / 2048), 256>>>(x);
    prep_xT<<<dim3(NPIX / 32, CCH / 32, BATCH), dim3(32, 8)>>>(x);
    prep_w<<<dim3(CCH * CCH / 256, 4), 256>>>(Wq, Wk, Wv, Wo);
    gemv<<<dim3(64, BATCH), 256>>>(Wq, sP, nullptr, qsP);
    gemv<<<dim3(64, BATCH), 256>>>(Wk, sP, nullptr, ksP);

    // Gram: G_b = x x^T, upper-triangle tiles, split-K4
    hgemm<false, true, true><<<dim3(10, 1, 32), 512, SMEM_FULL>>>(
        Xh, Xl, XTh, XTl, nullptr, nullptr, GpP,
        512, NPIX, 32, XS, XS, 0, (size_t)BATCH * WS);
    splitG<<<dim3(16, 16, BATCH), dim3(32, 8)>>>();

    // U_b = Wq G_b (3-pass)
    hgemm<false, true, false><<<dim3(4, 4, BATCH), 512, SMEM_FULL>>>(
        Wh + 0 * WS, Wl + 0 * WS, Gh, Gl, nullptr, nullptr, UP,
        512, 512, 16, 0, WS, 0, 0);

    lsoftmax<<<dim3(64, BATCH), 256>>>(Wk, bq, bk, gm);
    build_wy<<<dim3(64, BATCH), 256>>>(Wv, bv);
    gemv<<<dim3(64, BATCH), 256>>>(Wo, byP, bo, boP);

    // M_b = Wo * Wy_b (1-pass)
    hgemm<false, false, false><<<dim3(4, 4, BATCH), 512, SMEM_LITE>>>(
        Wh + 3 * WS, nullptr, Wyh, nullptr, nullptr, nullptr, MP,
        512, 512, 16, 0, WS, 0, 0);
    to_half<<<(unsigned)(BATCH * WS / 1024), 256>>>(MP, Mh);

    // out = M_b x + bias_b + x (1-pass)
    hgemm<true, false, false><<<dim3(NPIX / 128, 4, BATCH), 512, SMEM_LITE>>>(
        Mh, nullptr, Xh, nullptr, boP, x, out,
        NPIX, 512, 16, WS, XS, 512, 0);
}